// round 2
// baseline (speedup 1.0000x reference)
#include <cuda_runtime.h>
#include <cstdint>
#include <cstddef>

// ---------------------------------------------------------------------------
// Problem constants
// ---------------------------------------------------------------------------
#define B_SZ 8192
#define NU   1024
#define G3   3072
#define NT   30
#define CA   12
#define CR   64

static constexpr size_t OFF_AOH = 0;
static constexpr size_t OFF_APR = (size_t)B_SZ * NT * CA;                 // 2949120
static constexpr size_t OFF_ROH = 2 * (size_t)B_SZ * NT * CA;             // 5898240
static constexpr size_t OFF_RPR = OFF_ROH + (size_t)B_SZ * NT * CR;       // 21626880

// ---------------------------------------------------------------------------
// Device scratch (allocation-free rule: __device__ globals)
// ---------------------------------------------------------------------------
__device__ float g_X [(size_t)B_SZ * NU];   // GRU input x_t
__device__ float g_H [(size_t)B_SZ * NU];   // GRU state h_t
__device__ float g_Gx[(size_t)B_SZ * G3];   // x @ W_gru
__device__ float g_Gh[(size_t)B_SZ * G3];   // h @ U_gru

// ---------------------------------------------------------------------------
// Threefry-2x32 (20 rounds) — exact JAX/Random123 schedule
// ---------------------------------------------------------------------------
__device__ __forceinline__ void tf2x32(uint32_t k0, uint32_t k1,
                                       uint32_t x0, uint32_t x1,
                                       uint32_t& o0, uint32_t& o1) {
    uint32_t ks2 = k0 ^ k1 ^ 0x1BD11BDAu;
#define TFR(r) { x0 += x1; x1 = (x1 << (r)) | (x1 >> (32 - (r))); x1 ^= x0; }
    x0 += k0;  x1 += k1;
    TFR(13) TFR(15) TFR(26) TFR(6)
    x0 += k1;  x1 += ks2 + 1u;
    TFR(17) TFR(29) TFR(16) TFR(24)
    x0 += ks2; x1 += k0 + 2u;
    TFR(13) TFR(15) TFR(26) TFR(6)
    x0 += k0;  x1 += k1 + 3u;
    TFR(17) TFR(29) TFR(16) TFR(24)
    x0 += k1;  x1 += ks2 + 4u;
    TFR(13) TFR(15) TFR(26) TFR(6)
    x0 += ks2; x1 += k0 + 5u;
#undef TFR
    o0 = x0; o1 = x1;
}

// ---------------------------------------------------------------------------
// JAX *partitionable* threefry (default since JAX 0.4.36):
//   random_bits(key, 32, shape)[j] = w0 ^ w1  where (w0,w1)=TF(key, hi(j), lo(j))
//   (all our sizes < 2^32, so hi(j)=0)
//   split(key, n)[i] = (w0, w1) of TF(key, 0, i)
// ---------------------------------------------------------------------------
__device__ __forceinline__ uint32_t bits32(uint32_t k0, uint32_t k1, uint32_t j) {
    uint32_t o0, o1;
    tf2x32(k0, k1, 0u, j, o0, o1);
    return o0 ^ o1;
}

// JAX uniform->gumbel pipeline, bit-faithful.
// bits -> float in [0,1): bitcast((bits>>9)|0x3f800000) - 1
// u = max(tiny, f)  ((1-tiny) rounds to 1.0f, f*1+tiny == f for f>0)
// g = -log(-log(u))
__device__ __forceinline__ float gumbel_from_bits(uint32_t bits) {
    float f = __fsub_rn(__uint_as_float((bits >> 9) | 0x3f800000u), 1.0f);
    float u = fmaxf(f, 1.17549435e-38f);
    return -logf(-logf(u));
}

__device__ __forceinline__ float gumbel_at(uint32_t k0, uint32_t k1, uint32_t j) {
    return gumbel_from_bits(bits32(k0, k1, j));
}

// keys = split(key(42), 30) (foldlike); then split(keys[t], 2) -> (k_a, k_r)
__device__ __forceinline__ void step_keys(int t, uint32_t& ka0, uint32_t& ka1,
                                          uint32_t& kr0, uint32_t& kr1) {
    uint32_t kt0, kt1;
    tf2x32(0u, 42u, 0u, (uint32_t)t, kt0, kt1);   // keys[t]
    tf2x32(kt0, kt1, 0u, 0u, ka0, ka1);           // k_a = split(keys[t])[0]
    tf2x32(kt0, kt1, 0u, 1u, kr0, kr1);           // k_r = split(keys[t])[1]
}

// XLA logistic expansion: 0.5 + 0.5*tanh(0.5*x)
__device__ __forceinline__ float ref_sigmoid(float x) {
    return __fadd_rn(0.5f, __fmul_rn(0.5f, tanhf(__fmul_rn(0.5f, x))));
}

// first-index-tie warp argmax over (v, idx)
__device__ __forceinline__ int warp_argmax_i(float v, int idx) {
#pragma unroll
    for (int off = 16; off; off >>= 1) {
        float vo = __shfl_xor_sync(0xffffffffu, v, off);
        int   io = __shfl_xor_sync(0xffffffffu, idx, off);
        if (vo > v || (vo == v && io < idx)) { v = vo; idx = io; }
    }
    return idx;
}

// ---------------------------------------------------------------------------
// Init: h = s, x = 0
// ---------------------------------------------------------------------------
__global__ void k_init(const float* __restrict__ s) {
    size_t i = (size_t)blockIdx.x * blockDim.x + threadIdx.x;
    if (i < (size_t)B_SZ * NU) { g_H[i] = s[i]; g_X[i] = 0.0f; }
}

// ---------------------------------------------------------------------------
// GEMM: C[8192,3072] = A[8192,1024] @ B[1024,3072]
//   z==0: g_Gx = g_X @ W_gru ; z==1: g_Gh = g_H @ U_gru
// 128x128x16 tiles, cp.async double buffered, 8x8 per-thread microtile.
// ---------------------------------------------------------------------------
__device__ __forceinline__ uint32_t smem_u32(const void* p) {
    return (uint32_t)__cvta_generic_to_shared(p);
}
__device__ __forceinline__ void cp16(uint32_t dst, const void* src) {
    asm volatile("cp.async.cg.shared.global [%0], [%1], 16;" :: "r"(dst), "l"(src));
}
__device__ __forceinline__ void cp_commit() { asm volatile("cp.async.commit_group;"); }
template <int N> __device__ __forceinline__ void cp_wait() {
    asm volatile("cp.async.wait_group %0;" :: "n"(N));
}

__global__ __launch_bounds__(256, 2) void k_gemm(const float* __restrict__ Wg,
                                                 const float* __restrict__ Ug) {
    const float* A; const float* Bm; float* C;
    if (blockIdx.z == 0) { A = g_X; Bm = Wg; C = g_Gx; }
    else                 { A = g_H; Bm = Ug; C = g_Gh; }

    const int m0 = blockIdx.y * 128;
    const int n0 = blockIdx.x * 128;
    const int tid = threadIdx.x;
    const int tx = tid & 15, ty = tid >> 4;

    __shared__ float As[2][128][20];   // [m][k] + pad (rows 80B, 16B aligned)
    __shared__ float Bs[2][16][128];   // [k][n]

    float acc[8][8];
#pragma unroll
    for (int i = 0; i < 8; ++i)
#pragma unroll
        for (int j = 0; j < 8; ++j) acc[i][j] = 0.0f;

    auto load_tile = [&](int k0, int buf) {
#pragma unroll
        for (int i = 0; i < 2; ++i) {
            int ch = tid + 256 * i;
            int ar = ch >> 2, aq = ch & 3;
            cp16(smem_u32(&As[buf][ar][aq * 4]),
                 A + (size_t)(m0 + ar) * NU + k0 + aq * 4);
            int br = ch >> 5, bq = ch & 31;
            cp16(smem_u32(&Bs[buf][br][bq * 4]),
                 Bm + (size_t)(k0 + br) * G3 + n0 + bq * 4);
        }
    };

    load_tile(0, 0);
    cp_commit();

    const int NKIT = NU / 16;   // 64
    for (int it = 0; it < NKIT; ++it) {
        int buf = it & 1;
        if (it + 1 < NKIT) {
            load_tile((it + 1) * 16, (it + 1) & 1);
            cp_commit();
            cp_wait<1>();
        } else {
            cp_wait<0>();
        }
        __syncthreads();
#pragma unroll
        for (int k = 0; k < 16; ++k) {
            float a[8], bf[8];
#pragma unroll
            for (int i = 0; i < 8; ++i) a[i] = As[buf][ty * 8 + i][k];
            float4 b0 = *(const float4*)&Bs[buf][k][tx * 8];
            float4 b1 = *(const float4*)&Bs[buf][k][tx * 8 + 4];
            bf[0] = b0.x; bf[1] = b0.y; bf[2] = b0.z; bf[3] = b0.w;
            bf[4] = b1.x; bf[5] = b1.y; bf[6] = b1.z; bf[7] = b1.w;
#pragma unroll
            for (int i = 0; i < 8; ++i)
#pragma unroll
                for (int j = 0; j < 8; ++j)
                    acc[i][j] = fmaf(a[i], bf[j], acc[i][j]);
        }
        __syncthreads();
    }

#pragma unroll
    for (int i = 0; i < 8; ++i) {
        size_t row = (size_t)(m0 + ty * 8 + i) * G3 + n0 + tx * 8;
        float4 v0 = make_float4(acc[i][0], acc[i][1], acc[i][2], acc[i][3]);
        float4 v1 = make_float4(acc[i][4], acc[i][5], acc[i][6], acc[i][7]);
        *(float4*)&C[row]     = v0;
        *(float4*)&C[row + 4] = v1;
    }
}

// ---------------------------------------------------------------------------
// GRU gate combine (reference association order, explicit roundings)
// ---------------------------------------------------------------------------
__global__ __launch_bounds__(256) void k_combine(const float* __restrict__ bgru) {
    int i = blockIdx.x * 256 + threadIdx.x;           // exactly B_SZ*NU threads
    int u = i & (NU - 1);
    int b = i >> 10;
    const float* gx = g_Gx + (size_t)b * G3;
    const float* gh = g_Gh + (size_t)b * G3;

    float xz = __fadd_rn(gx[u],          bgru[u]);
    float xr = __fadd_rn(gx[u + NU],     bgru[u + NU]);
    float xn = __fadd_rn(gx[u + 2 * NU], bgru[u + 2 * NU]);
    float hz = gh[u], hr = gh[u + NU], hn = gh[u + 2 * NU];

    float z = ref_sigmoid(__fadd_rn(xz, hz));
    float r = ref_sigmoid(__fadd_rn(xr, hr));
    float n = tanhf(__fadd_rn(xn, __fmul_rn(r, hn)));
    float h = g_H[i];
    g_H[i] = __fadd_rn(__fmul_rn(z, h), __fmul_rn(__fsub_rn(1.0f, z), n));
}

// ---------------------------------------------------------------------------
// Logits + softmax + gumbel-argmax sampling + outputs + x_next
// 16 rows per block, 256 threads. Dynamic smem: h rows (padded) + logits.
// ---------------------------------------------------------------------------
static constexpr int SROW = 1032;  // 1024 + 8 pad (bank shift, 16B-aligned rows)
static constexpr int SMEM_SAMPLE = (16 * SROW + 16 * 80) * 4;

__global__ __launch_bounds__(256) void k_sample(
    int t,
    const float* __restrict__ Wang, const float* __restrict__ bang,
    const float* __restrict__ Wrad, const float* __restrict__ brad,
    const float* __restrict__ Wenc, const float* __restrict__ benc,
    float* __restrict__ out) {

    extern __shared__ float smem[];
    float* sh = smem;                 // [16][SROW]
    float* sl = smem + 16 * SROW;     // [16][80] logits
    __shared__ int s_aidx[16];
    __shared__ int s_ridx[16];

    const int tid = threadIdx.x;
    const int b0 = blockIdx.x * 16;

    // load 16 h rows (float4, padded rows)
    const float4* src = (const float4*)(g_H + (size_t)b0 * NU);
    for (int v = tid; v < 16 * 256; v += 256) {
        int row = v >> 8, c4 = v & 255;
        ((float4*)(sh + row * SROW))[c4] = src[row * 256 + c4];
    }
    __syncthreads();

    // 16*76 dot products over K=1024 (4 accumulators each, fma chains)
    for (int l = tid; l < 16 * 76; l += 256) {
        int row = l / 76, c = l - row * 76;
        const float* hrow = sh + row * SROW;
        const float* wcol; int ldw; float bias;
        if (c < CA) { wcol = Wang + c;        ldw = CA; bias = bang[c]; }
        else        { wcol = Wrad + (c - CA); ldw = CR; bias = brad[c - CA]; }
        float a0 = 0.f, a1 = 0.f, a2 = 0.f, a3 = 0.f;
#pragma unroll 4
        for (int k = 0; k < NU; k += 4) {
            a0 = fmaf(hrow[k],     __ldg(wcol + (size_t)k * ldw),       a0);
            a1 = fmaf(hrow[k + 1], __ldg(wcol + (size_t)(k + 1) * ldw), a1);
            a2 = fmaf(hrow[k + 2], __ldg(wcol + (size_t)(k + 2) * ldw), a2);
            a3 = fmaf(hrow[k + 3], __ldg(wcol + (size_t)(k + 3) * ldw), a3);
        }
        sl[row * 80 + c] =
            __fadd_rn(__fadd_rn(__fadd_rn(a0, a2), __fadd_rn(a1, a3)), bias);
    }
    __syncthreads();

    uint32_t ka0, ka1, kr0, kr1;
    step_keys(t, ka0, ka1, kr0, kr1);

    const int wid = tid >> 5, lane = tid & 31;
    const float NEG_INF = __int_as_float(0xff800000);

    for (int rr = wid; rr < 16; rr += 8) {
        int b = b0 + rr;

        // ---- angle (12 categories) ----
        float lg = (lane < CA) ? sl[rr * 80 + lane] : NEG_INF;
        float m = lg;
#pragma unroll
        for (int off = 16; off; off >>= 1)
            m = fmaxf(m, __shfl_xor_sync(0xffffffffu, m, off));
        float e = (lane < CA) ? expf(__fsub_rn(lg, m)) : 0.0f;
        float ssum = e;
#pragma unroll
        for (int off = 16; off; off >>= 1)
            ssum += __shfl_xor_sync(0xffffffffu, ssum, off);

        float y = NEG_INF;
        if (lane < CA) {
            uint32_t j = (uint32_t)b * CA + lane;
            float g = gumbel_at(ka0, ka1, j);
            y = __fadd_rn(g, lg);
        }
        int aidx = warp_argmax_i(y, lane);
        if (lane < CA) {
            size_t base = ((size_t)b * NT + t) * CA;
            out[OFF_AOH + base + lane] = (lane == aidx) ? 1.0f : 0.0f;
            out[OFF_APR + base + lane] = __fdiv_rn(e, ssum);
        }

        // ---- radius (64 categories, 2 per lane) ----
        float l0v = sl[rr * 80 + CA + lane];
        float l1v = sl[rr * 80 + CA + lane + 32];
        float m2 = fmaxf(l0v, l1v);
#pragma unroll
        for (int off = 16; off; off >>= 1)
            m2 = fmaxf(m2, __shfl_xor_sync(0xffffffffu, m2, off));
        float e0 = expf(__fsub_rn(l0v, m2));
        float e1 = expf(__fsub_rn(l1v, m2));
        float s2 = e0 + e1;
#pragma unroll
        for (int off = 16; off; off >>= 1)
            s2 += __shfl_xor_sync(0xffffffffu, s2, off);

        uint32_t j0 = (uint32_t)b * CR + lane;
        float y0 = __fadd_rn(gumbel_at(kr0, kr1, j0),      l0v);
        float y1 = __fadd_rn(gumbel_at(kr0, kr1, j0 + 32), l1v);
        float yb; int ib;
        if (y1 > y0) { yb = y1; ib = lane + 32; } else { yb = y0; ib = lane; }
        int ridx = warp_argmax_i(yb, ib);

        size_t baser = ((size_t)b * NT + t) * CR;
        out[OFF_ROH + baser + lane]      = (ridx == lane)      ? 1.0f : 0.0f;
        out[OFF_ROH + baser + lane + 32] = (ridx == lane + 32) ? 1.0f : 0.0f;
        out[OFF_RPR + baser + lane]      = __fdiv_rn(e0, s2);
        out[OFF_RPR + baser + lane + 32] = __fdiv_rn(e1, s2);

        if (lane == 0) { s_aidx[rr] = aidx; s_ridx[rr] = ridx; }
    }
    __syncthreads();

    // x_next = W_enc[a] + W_enc[12+r] + b_enc  (bit-exact: only 2 nonzeros)
    for (int v = tid; v < 16 * NU; v += 256) {
        int row = v >> 10, u = v & (NU - 1);
        int ai = s_aidx[row], ri = s_ridx[row];
        float val = __fadd_rn(
            __fadd_rn(__ldg(Wenc + (size_t)ai * NU + u),
                      __ldg(Wenc + (size_t)(CA + ri) * NU + u)),
            benc[u]);
        g_X[(size_t)(b0 + row) * NU + u] = val;
    }
}

// ---------------------------------------------------------------------------
// Launch
// ---------------------------------------------------------------------------
extern "C" void kernel_launch(void* const* d_in, const int* in_sizes, int n_in,
                              void* d_out, int out_size) {
    const float* s    = (const float*)d_in[0];
    const float* Wenc = (const float*)d_in[1];
    const float* benc = (const float*)d_in[2];
    const float* Wgru = (const float*)d_in[3];
    const float* Ugru = (const float*)d_in[4];
    const float* bgru = (const float*)d_in[5];
    const float* Wang = (const float*)d_in[6];
    const float* bang = (const float*)d_in[7];
    const float* Wrad = (const float*)d_in[8];
    const float* brad = (const float*)d_in[9];
    float* out = (float*)d_out;

    cudaFuncSetAttribute(k_sample, cudaFuncAttributeMaxDynamicSharedMemorySize,
                         SMEM_SAMPLE);

    k_init<<<(B_SZ * NU + 255) / 256, 256>>>(s);

    for (int t = 0; t < NT; ++t) {
        k_gemm<<<dim3(G3 / 128, B_SZ / 128, 2), 256>>>(Wgru, Ugru);
        k_combine<<<(B_SZ * NU) / 256, 256>>>(bgru);
        k_sample<<<B_SZ / 16, 256, SMEM_SAMPLE>>>(t, Wang, bang, Wrad, brad,
                                                  Wenc, benc, out);
    }
}

// round 3
// speedup vs baseline: 1.6937x; 1.6937x over previous
#include <cuda_runtime.h>
#include <cstdint>
#include <cstddef>

// ---------------------------------------------------------------------------
// Problem constants
// ---------------------------------------------------------------------------
#define B_SZ 8192
#define NU   1024
#define G3   3072
#define NT   30
#define CA   12
#define CR   64

static constexpr size_t OFF_AOH = 0;
static constexpr size_t OFF_APR = (size_t)B_SZ * NT * CA;
static constexpr size_t OFF_ROH = 2 * (size_t)B_SZ * NT * CA;
static constexpr size_t OFF_RPR = OFF_ROH + (size_t)B_SZ * NT * CR;

// ---------------------------------------------------------------------------
// Device scratch (allocation-free rule: __device__ globals)
// ---------------------------------------------------------------------------
__device__ float g_H  [(size_t)B_SZ * NU];   // GRU state h_t
__device__ float g_Gh [(size_t)B_SZ * G3];   // h @ U_gru
__device__ float g_P  [76 * G3];             // W_enc @ W_gru  (L2-resident)
__device__ float g_pb [G3];                  // b_enc @ W_gru
__device__ float g_WT [76 * NU];             // [W_ang | W_rad]^T, row-major [c][k]
__device__ int   g_Aidx[B_SZ];
__device__ int   g_Ridx[B_SZ];

// ---------------------------------------------------------------------------
// Threefry-2x32 (20 rounds) — exact JAX/Random123 schedule
// ---------------------------------------------------------------------------
__device__ __forceinline__ void tf2x32(uint32_t k0, uint32_t k1,
                                       uint32_t x0, uint32_t x1,
                                       uint32_t& o0, uint32_t& o1) {
    uint32_t ks2 = k0 ^ k1 ^ 0x1BD11BDAu;
#define TFR(r) { x0 += x1; x1 = (x1 << (r)) | (x1 >> (32 - (r))); x1 ^= x0; }
    x0 += k0;  x1 += k1;
    TFR(13) TFR(15) TFR(26) TFR(6)
    x0 += k1;  x1 += ks2 + 1u;
    TFR(17) TFR(29) TFR(16) TFR(24)
    x0 += ks2; x1 += k0 + 2u;
    TFR(13) TFR(15) TFR(26) TFR(6)
    x0 += k0;  x1 += k1 + 3u;
    TFR(17) TFR(29) TFR(16) TFR(24)
    x0 += k1;  x1 += ks2 + 4u;
    TFR(13) TFR(15) TFR(26) TFR(6)
    x0 += ks2; x1 += k0 + 5u;
#undef TFR
    o0 = x0; o1 = x1;
}

// JAX partitionable threefry: bits[j] = w0 ^ w1 of TF(key, 0, j)
__device__ __forceinline__ uint32_t bits32(uint32_t k0, uint32_t k1, uint32_t j) {
    uint32_t o0, o1;
    tf2x32(k0, k1, 0u, j, o0, o1);
    return o0 ^ o1;
}

// bits -> uniform[0,1) -> gumbel, bit-faithful to JAX
__device__ __forceinline__ float gumbel_from_bits(uint32_t bits) {
    float f = __fsub_rn(__uint_as_float((bits >> 9) | 0x3f800000u), 1.0f);
    float u = fmaxf(f, 1.17549435e-38f);
    return -logf(-logf(u));
}

__device__ __forceinline__ float gumbel_at(uint32_t k0, uint32_t k1, uint32_t j) {
    return gumbel_from_bits(bits32(k0, k1, j));
}

// keys = split(key(42), 30) (foldlike); split(keys[t], 2) -> (k_a, k_r)
__device__ __forceinline__ void step_keys(int t, uint32_t& ka0, uint32_t& ka1,
                                          uint32_t& kr0, uint32_t& kr1) {
    uint32_t kt0, kt1;
    tf2x32(0u, 42u, 0u, (uint32_t)t, kt0, kt1);
    tf2x32(kt0, kt1, 0u, 0u, ka0, ka1);
    tf2x32(kt0, kt1, 0u, 1u, kr0, kr1);
}

// XLA logistic expansion: 0.5 + 0.5*tanh(0.5*x)
__device__ __forceinline__ float ref_sigmoid(float x) {
    return __fadd_rn(0.5f, __fmul_rn(0.5f, tanhf(__fmul_rn(0.5f, x))));
}

// first-index-tie warp argmax over (v, idx)
__device__ __forceinline__ int warp_argmax_i(float v, int idx) {
#pragma unroll
    for (int off = 16; off; off >>= 1) {
        float vo = __shfl_xor_sync(0xffffffffu, v, off);
        int   io = __shfl_xor_sync(0xffffffffu, idx, off);
        if (vo > v || (vo == v && io < idx)) { v = vo; idx = io; }
    }
    return idx;
}

// ---------------------------------------------------------------------------
// Init: h = s
// ---------------------------------------------------------------------------
__global__ void k_init(const float* __restrict__ s) {
    size_t i = (size_t)blockIdx.x * blockDim.x + threadIdx.x;
    if (i < (size_t)B_SZ * NU) g_H[i] = s[i];
}

// ---------------------------------------------------------------------------
// Precompute P = W_enc @ W_gru (rows 0..75) and pb = b_enc @ W_gru (row 76)
// ---------------------------------------------------------------------------
__global__ __launch_bounds__(256) void k_prepP(const float* __restrict__ Wenc,
                                               const float* __restrict__ benc,
                                               const float* __restrict__ Wgru) {
    int j = blockIdx.x * 256 + threadIdx.x;      // 0..3071
    int row = blockIdx.y;                        // 0..76
    const float* v = (row < 76) ? (Wenc + (size_t)row * NU) : benc;
    float a0 = 0.f, a1 = 0.f, a2 = 0.f, a3 = 0.f;
#pragma unroll 4
    for (int u = 0; u < NU; u += 4) {
        a0 = fmaf(v[u],     Wgru[(size_t)u * G3 + j],       a0);
        a1 = fmaf(v[u + 1], Wgru[(size_t)(u + 1) * G3 + j], a1);
        a2 = fmaf(v[u + 2], Wgru[(size_t)(u + 2) * G3 + j], a2);
        a3 = fmaf(v[u + 3], Wgru[(size_t)(u + 3) * G3 + j], a3);
    }
    float r = __fadd_rn(__fadd_rn(a0, a2), __fadd_rn(a1, a3));
    if (row < 76) g_P[(size_t)row * G3 + j] = r;
    else          g_pb[j] = r;
}

// Precompute WT[c][k] = (c<12 ? W_ang[k][c] : W_rad[k][c-12])
__global__ void k_prepWT(const float* __restrict__ Wang,
                         const float* __restrict__ Wrad) {
    int i = blockIdx.x * 256 + threadIdx.x;
    if (i >= 76 * NU) return;
    int c = i >> 10, k = i & (NU - 1);
    g_WT[i] = (c < CA) ? Wang[(size_t)k * CA + c]
                       : Wrad[(size_t)k * CR + (c - CA)];
}

// ---------------------------------------------------------------------------
// GEMM: g_Gh[8192,3072] = g_H[8192,1024] @ U_gru[1024,3072]
// 128x128x16 tiles, cp.async double buffered, 8x8 per-thread microtile.
// ---------------------------------------------------------------------------
__device__ __forceinline__ uint32_t smem_u32(const void* p) {
    return (uint32_t)__cvta_generic_to_shared(p);
}
__device__ __forceinline__ void cp16(uint32_t dst, const void* src) {
    asm volatile("cp.async.cg.shared.global [%0], [%1], 16;" :: "r"(dst), "l"(src));
}
__device__ __forceinline__ void cp_commit() { asm volatile("cp.async.commit_group;"); }
template <int N> __device__ __forceinline__ void cp_wait() {
    asm volatile("cp.async.wait_group %0;" :: "n"(N));
}

__global__ __launch_bounds__(256, 2) void k_gemm(const float* __restrict__ Ug) {
    const float* A = g_H;
    const float* Bm = Ug;
    float* C = g_Gh;

    const int m0 = blockIdx.y * 128;
    const int n0 = blockIdx.x * 128;
    const int tid = threadIdx.x;
    const int tx = tid & 15, ty = tid >> 4;

    __shared__ float As[2][128][20];
    __shared__ float Bs[2][16][128];

    float acc[8][8];
#pragma unroll
    for (int i = 0; i < 8; ++i)
#pragma unroll
        for (int j = 0; j < 8; ++j) acc[i][j] = 0.0f;

    auto load_tile = [&](int k0, int buf) {
#pragma unroll
        for (int i = 0; i < 2; ++i) {
            int ch = tid + 256 * i;
            int ar = ch >> 2, aq = ch & 3;
            cp16(smem_u32(&As[buf][ar][aq * 4]),
                 A + (size_t)(m0 + ar) * NU + k0 + aq * 4);
            int br = ch >> 5, bq = ch & 31;
            cp16(smem_u32(&Bs[buf][br][bq * 4]),
                 Bm + (size_t)(k0 + br) * G3 + n0 + bq * 4);
        }
    };

    load_tile(0, 0);
    cp_commit();

    const int NKIT = NU / 16;   // 64
    for (int it = 0; it < NKIT; ++it) {
        int buf = it & 1;
        if (it + 1 < NKIT) {
            load_tile((it + 1) * 16, (it + 1) & 1);
            cp_commit();
            cp_wait<1>();
        } else {
            cp_wait<0>();
        }
        __syncthreads();
#pragma unroll
        for (int k = 0; k < 16; ++k) {
            float a[8], bf[8];
#pragma unroll
            for (int i = 0; i < 8; ++i) a[i] = As[buf][ty * 8 + i][k];
            float4 b0 = *(const float4*)&Bs[buf][k][tx * 8];
            float4 b1 = *(const float4*)&Bs[buf][k][tx * 8 + 4];
            bf[0] = b0.x; bf[1] = b0.y; bf[2] = b0.z; bf[3] = b0.w;
            bf[4] = b1.x; bf[5] = b1.y; bf[6] = b1.z; bf[7] = b1.w;
#pragma unroll
            for (int i = 0; i < 8; ++i)
#pragma unroll
                for (int j = 0; j < 8; ++j)
                    acc[i][j] = fmaf(a[i], bf[j], acc[i][j]);
        }
        __syncthreads();
    }

#pragma unroll
    for (int i = 0; i < 8; ++i) {
        size_t row = (size_t)(m0 + ty * 8 + i) * G3 + n0 + tx * 8;
        *(float4*)&C[row]     = make_float4(acc[i][0], acc[i][1], acc[i][2], acc[i][3]);
        *(float4*)&C[row + 4] = make_float4(acc[i][4], acc[i][5], acc[i][6], acc[i][7]);
    }
}

// ---------------------------------------------------------------------------
// GRU gate combine with fused 2-hot Gx gather:
//   gx = P[a] + P[12+r] + pb   (t>0);  gx = 0  (t==0, since x0 = 0)
// ---------------------------------------------------------------------------
__global__ __launch_bounds__(256) void k_combine(const float* __restrict__ bgru,
                                                 int t) {
    int i = blockIdx.x * 256 + threadIdx.x;           // exactly B_SZ*NU threads
    int u = i & (NU - 1);
    int b = i >> 10;

    float gx0, gx1, gx2;
    if (t == 0) {
        gx0 = gx1 = gx2 = 0.0f;
    } else {
        int a  = g_Aidx[b];
        int rr = g_Ridx[b];
        const float* Pa = g_P + (size_t)a * G3;
        const float* Pr = g_P + (size_t)(CA + rr) * G3;
        gx0 = __fadd_rn(__fadd_rn(Pa[u],          Pr[u]),          g_pb[u]);
        gx1 = __fadd_rn(__fadd_rn(Pa[u + NU],     Pr[u + NU]),     g_pb[u + NU]);
        gx2 = __fadd_rn(__fadd_rn(Pa[u + 2 * NU], Pr[u + 2 * NU]), g_pb[u + 2 * NU]);
    }

    const float* gh = g_Gh + (size_t)b * G3;
    float xz = __fadd_rn(gx0, bgru[u]);
    float xr = __fadd_rn(gx1, bgru[u + NU]);
    float xn = __fadd_rn(gx2, bgru[u + 2 * NU]);
    float hz = gh[u], hr = gh[u + NU], hn = gh[u + 2 * NU];

    float z = ref_sigmoid(__fadd_rn(xz, hz));
    float r = ref_sigmoid(__fadd_rn(xr, hr));
    float n = tanhf(__fadd_rn(xn, __fmul_rn(r, hn)));
    float h = g_H[i];
    g_H[i] = __fadd_rn(__fmul_rn(z, h), __fmul_rn(__fsub_rn(1.0f, z), n));
}

// ---------------------------------------------------------------------------
// Logits (via transposed weights) + softmax + gumbel-argmax + outputs + idx
// ---------------------------------------------------------------------------
static constexpr int SROW = 1028;  // 1024 + 4 floats skew; rows 16B-aligned
static constexpr int SMEM_SAMPLE = (16 * SROW + 16 * 80) * 4;

__global__ __launch_bounds__(256) void k_sample(
    int t,
    const float* __restrict__ bang, const float* __restrict__ brad,
    float* __restrict__ out) {

    extern __shared__ float smem[];
    float* sh = smem;                 // [16][SROW]
    float* sl = smem + 16 * SROW;     // [16][80] logits
    __shared__ int s_aidx[16];
    __shared__ int s_ridx[16];

    const int tid = threadIdx.x;
    const int b0 = blockIdx.x * 16;

    // stage 16 h rows (float4, skewed rows)
    const float4* src = (const float4*)(g_H + (size_t)b0 * NU);
    float4* sh4 = (float4*)sh;
    for (int v = tid; v < 16 * 256; v += 256) {
        int row = v >> 8, c4 = v & 255;
        sh4[row * (SROW / 4) + c4] = src[row * 256 + c4];
    }
    __syncthreads();

    // 16 rows x 76 logits; WT rows contiguous, broadcast within warp.
    // Accumulator pairing identical to the R2 kernel (a0:k%4==0, ...).
    for (int l = tid; l < 16 * 76; l += 256) {
        int c = l >> 4, row = l & 15;
        const float4* w4 = (const float4*)(g_WT + (size_t)c * NU);
        const float4* h4 = sh4 + row * (SROW / 4);
        float a0 = 0.f, a1 = 0.f, a2 = 0.f, a3 = 0.f;
#pragma unroll 4
        for (int k = 0; k < 256; ++k) {
            float4 w = w4[k];
            float4 hv = h4[k];
            a0 = fmaf(hv.x, w.x, a0);
            a1 = fmaf(hv.y, w.y, a1);
            a2 = fmaf(hv.z, w.z, a2);
            a3 = fmaf(hv.w, w.w, a3);
        }
        float bias = (c < CA) ? bang[c] : brad[c - CA];
        sl[row * 80 + c] =
            __fadd_rn(__fadd_rn(__fadd_rn(a0, a2), __fadd_rn(a1, a3)), bias);
    }
    __syncthreads();

    uint32_t ka0, ka1, kr0, kr1;
    step_keys(t, ka0, ka1, kr0, kr1);

    const int wid = tid >> 5, lane = tid & 31;
    const float NEG_INF = __int_as_float(0xff800000);

    for (int rr = wid; rr < 16; rr += 8) {
        int b = b0 + rr;

        // ---- angle (12 categories) ----
        float lg = (lane < CA) ? sl[rr * 80 + lane] : NEG_INF;
        float m = lg;
#pragma unroll
        for (int off = 16; off; off >>= 1)
            m = fmaxf(m, __shfl_xor_sync(0xffffffffu, m, off));
        float e = (lane < CA) ? expf(__fsub_rn(lg, m)) : 0.0f;
        float ssum = e;
#pragma unroll
        for (int off = 16; off; off >>= 1)
            ssum += __shfl_xor_sync(0xffffffffu, ssum, off);

        float y = NEG_INF;
        if (lane < CA) {
            uint32_t j = (uint32_t)b * CA + lane;
            y = __fadd_rn(gumbel_at(ka0, ka1, j), lg);
        }
        int aidx = warp_argmax_i(y, lane);
        if (lane < CA) {
            size_t base = ((size_t)b * NT + t) * CA;
            out[OFF_AOH + base + lane] = (lane == aidx) ? 1.0f : 0.0f;
            out[OFF_APR + base + lane] = __fdiv_rn(e, ssum);
        }

        // ---- radius (64 categories, 2 per lane) ----
        float l0v = sl[rr * 80 + CA + lane];
        float l1v = sl[rr * 80 + CA + lane + 32];
        float m2 = fmaxf(l0v, l1v);
#pragma unroll
        for (int off = 16; off; off >>= 1)
            m2 = fmaxf(m2, __shfl_xor_sync(0xffffffffu, m2, off));
        float e0 = expf(__fsub_rn(l0v, m2));
        float e1 = expf(__fsub_rn(l1v, m2));
        float s2 = e0 + e1;
#pragma unroll
        for (int off = 16; off; off >>= 1)
            s2 += __shfl_xor_sync(0xffffffffu, s2, off);

        uint32_t j0 = (uint32_t)b * CR + lane;
        float y0 = __fadd_rn(gumbel_at(kr0, kr1, j0),      l0v);
        float y1 = __fadd_rn(gumbel_at(kr0, kr1, j0 + 32), l1v);
        float yb; int ib;
        if (y1 > y0) { yb = y1; ib = lane + 32; } else { yb = y0; ib = lane; }
        int ridx = warp_argmax_i(yb, ib);

        size_t baser = ((size_t)b * NT + t) * CR;
        out[OFF_ROH + baser + lane]      = (ridx == lane)      ? 1.0f : 0.0f;
        out[OFF_ROH + baser + lane + 32] = (ridx == lane + 32) ? 1.0f : 0.0f;
        out[OFF_RPR + baser + lane]      = __fdiv_rn(e0, s2);
        out[OFF_RPR + baser + lane + 32] = __fdiv_rn(e1, s2);

        if (lane == 0) { s_aidx[rr] = aidx; s_ridx[rr] = ridx; }
    }
    __syncthreads();

    if (tid < 16) {
        g_Aidx[b0 + tid] = s_aidx[tid];
        g_Ridx[b0 + tid] = s_ridx[tid];
    }
}

// ---------------------------------------------------------------------------
// Launch
// ---------------------------------------------------------------------------
extern "C" void kernel_launch(void* const* d_in, const int* in_sizes, int n_in,
                              void* d_out, int out_size) {
    const float* s    = (const float*)d_in[0];
    const float* Wenc = (const float*)d_in[1];
    const float* benc = (const float*)d_in[2];
    const float* Wgru = (const float*)d_in[3];
    const float* Ugru = (const float*)d_in[4];
    const float* bgru = (const float*)d_in[5];
    const float* Wang = (const float*)d_in[6];
    const float* bang = (const float*)d_in[7];
    const float* Wrad = (const float*)d_in[8];
    const float* brad = (const float*)d_in[9];
    float* out = (float*)d_out;

    cudaFuncSetAttribute(k_sample, cudaFuncAttributeMaxDynamicSharedMemorySize,
                         SMEM_SAMPLE);

    k_init<<<(B_SZ * NU + 255) / 256, 256>>>(s);
    k_prepP<<<dim3(G3 / 256, 77), 256>>>(Wenc, benc, Wgru);
    k_prepWT<<<(76 * NU + 255) / 256, 256>>>(Wang, Wrad);

    for (int t = 0; t < NT; ++t) {
        k_gemm<<<dim3(G3 / 128, B_SZ / 128), 256>>>(Ugru);
        k_combine<<<(B_SZ * NU) / 256, 256>>>(bgru, t);
        k_sample<<<B_SZ / 16, 256, SMEM_SAMPLE>>>(t, bang, brad, out);
    }
}

// round 6
// speedup vs baseline: 2.1551x; 1.2724x over previous
#include <cuda_runtime.h>
#include <cstdint>
#include <cstddef>

// ---------------------------------------------------------------------------
// Problem constants
// ---------------------------------------------------------------------------
#define B_SZ 8192
#define NU   1024
#define G3   3072
#define NT   30
#define CA   12
#define CR   64

static constexpr size_t OFF_AOH = 0;
static constexpr size_t OFF_APR = (size_t)B_SZ * NT * CA;
static constexpr size_t OFF_ROH = 2 * (size_t)B_SZ * NT * CA;
static constexpr size_t OFF_RPR = OFF_ROH + (size_t)B_SZ * NT * CR;

// ---------------------------------------------------------------------------
// Device scratch
// ---------------------------------------------------------------------------
__device__ float g_H   [(size_t)B_SZ * NU];
__device__ float g_Hhi [(size_t)B_SZ * NU];   // tf32-rounded h
__device__ float g_Hlo [(size_t)B_SZ * NU];   // tf32 residual
__device__ float g_Gh  [(size_t)B_SZ * G3];
__device__ float g_UhiT[(size_t)G3 * NU];     // U^T hi, [n][k]
__device__ float g_UloT[(size_t)G3 * NU];     // U^T lo
__device__ float g_P   [76 * G3];
__device__ float g_pb  [G3];
__device__ float g_WT  [76 * NU];
__device__ int   g_Aidx[B_SZ];
__device__ int   g_Ridx[B_SZ];

// ---------------------------------------------------------------------------
// tf32 split
// ---------------------------------------------------------------------------
__device__ __forceinline__ void tf32_split(float x, float& hi, float& lo) {
    uint32_t h, l;
    asm("cvt.rna.tf32.f32 %0, %1;" : "=r"(h) : "f"(x));
    hi = __uint_as_float(h);
    float r = __fsub_rn(x, hi);
    asm("cvt.rna.tf32.f32 %0, %1;" : "=r"(l) : "f"(r));
    lo = __uint_as_float(l);
}

// ---------------------------------------------------------------------------
// Threefry-2x32 (20 rounds), JAX partitionable derivations
// ---------------------------------------------------------------------------
__device__ __forceinline__ void tf2x32(uint32_t k0, uint32_t k1,
                                       uint32_t x0, uint32_t x1,
                                       uint32_t& o0, uint32_t& o1) {
    uint32_t ks2 = k0 ^ k1 ^ 0x1BD11BDAu;
#define TFR(r) { x0 += x1; x1 = (x1 << (r)) | (x1 >> (32 - (r))); x1 ^= x0; }
    x0 += k0;  x1 += k1;
    TFR(13) TFR(15) TFR(26) TFR(6)
    x0 += k1;  x1 += ks2 + 1u;
    TFR(17) TFR(29) TFR(16) TFR(24)
    x0 += ks2; x1 += k0 + 2u;
    TFR(13) TFR(15) TFR(26) TFR(6)
    x0 += k0;  x1 += k1 + 3u;
    TFR(17) TFR(29) TFR(16) TFR(24)
    x0 += k1;  x1 += ks2 + 4u;
    TFR(13) TFR(15) TFR(26) TFR(6)
    x0 += ks2; x1 += k0 + 5u;
#undef TFR
    o0 = x0; o1 = x1;
}

__device__ __forceinline__ uint32_t bits32(uint32_t k0, uint32_t k1, uint32_t j) {
    uint32_t o0, o1;
    tf2x32(k0, k1, 0u, j, o0, o1);
    return o0 ^ o1;
}

__device__ __forceinline__ float gumbel_from_bits(uint32_t bits) {
    float f = __fsub_rn(__uint_as_float((bits >> 9) | 0x3f800000u), 1.0f);
    float u = fmaxf(f, 1.17549435e-38f);
    return -logf(-logf(u));
}

__device__ __forceinline__ float gumbel_at(uint32_t k0, uint32_t k1, uint32_t j) {
    return gumbel_from_bits(bits32(k0, k1, j));
}

__device__ __forceinline__ void step_keys(int t, uint32_t& ka0, uint32_t& ka1,
                                          uint32_t& kr0, uint32_t& kr1) {
    uint32_t kt0, kt1;
    tf2x32(0u, 42u, 0u, (uint32_t)t, kt0, kt1);
    tf2x32(kt0, kt1, 0u, 0u, ka0, ka1);
    tf2x32(kt0, kt1, 0u, 1u, kr0, kr1);
}

__device__ __forceinline__ float ref_sigmoid(float x) {
    return __fadd_rn(0.5f, __fmul_rn(0.5f, tanhf(__fmul_rn(0.5f, x))));
}

__device__ __forceinline__ int warp_argmax_i(float v, int idx) {
#pragma unroll
    for (int off = 16; off; off >>= 1) {
        float vo = __shfl_xor_sync(0xffffffffu, v, off);
        int   io = __shfl_xor_sync(0xffffffffu, idx, off);
        if (vo > v || (vo == v && io < idx)) { v = vo; idx = io; }
    }
    return idx;
}

// ---------------------------------------------------------------------------
// cp.async helpers
// ---------------------------------------------------------------------------
__device__ __forceinline__ uint32_t smem_u32(const void* p) {
    return (uint32_t)__cvta_generic_to_shared(p);
}
__device__ __forceinline__ void cp16(uint32_t dst, const void* src) {
    asm volatile("cp.async.cg.shared.global [%0], [%1], 16;" :: "r"(dst), "l"(src));
}
__device__ __forceinline__ void cp_commit() { asm volatile("cp.async.commit_group;"); }
template <int N> __device__ __forceinline__ void cp_wait() {
    asm volatile("cp.async.wait_group %0;" :: "n"(N));
}

// ---------------------------------------------------------------------------
// warp-level tf32 MMA (sm_80+ path, works at compute_100 target)
// ---------------------------------------------------------------------------
__device__ __forceinline__ void mma_tf32(float* c, const uint32_t* a,
                                         const uint32_t* b) {
    asm volatile(
        "mma.sync.aligned.m16n8k8.row.col.f32.tf32.tf32.f32 "
        "{%0,%1,%2,%3}, {%4,%5,%6,%7}, {%8,%9}, {%0,%1,%2,%3};"
        : "+f"(c[0]), "+f"(c[1]), "+f"(c[2]), "+f"(c[3])
        : "r"(a[0]), "r"(a[1]), "r"(a[2]), "r"(a[3]), "r"(b[0]), "r"(b[1]));
}

// ---------------------------------------------------------------------------
// Init / prep
// ---------------------------------------------------------------------------
__global__ void k_init(const float* __restrict__ s) {
    size_t i = (size_t)blockIdx.x * blockDim.x + threadIdx.x;
    if (i < (size_t)B_SZ * NU) {
        float v = s[i];
        g_H[i] = v;
        float hi, lo;
        tf32_split(v, hi, lo);
        g_Hhi[i] = hi; g_Hlo[i] = lo;
    }
}

__global__ void k_prepU(const float* __restrict__ Ugru) {
    size_t i = (size_t)blockIdx.x * blockDim.x + threadIdx.x;
    if (i >= (size_t)G3 * NU) return;
    int n = (int)(i >> 10), k = (int)(i & (NU - 1));
    float v = Ugru[(size_t)k * G3 + n];
    float hi, lo;
    tf32_split(v, hi, lo);
    g_UhiT[i] = hi; g_UloT[i] = lo;
}

__global__ __launch_bounds__(256) void k_prepP(const float* __restrict__ Wenc,
                                               const float* __restrict__ benc,
                                               const float* __restrict__ Wgru) {
    int j = blockIdx.x * 256 + threadIdx.x;
    int row = blockIdx.y;
    const float* v = (row < 76) ? (Wenc + (size_t)row * NU) : benc;
    float a0 = 0.f, a1 = 0.f, a2 = 0.f, a3 = 0.f;
#pragma unroll 4
    for (int u = 0; u < NU; u += 4) {
        a0 = fmaf(v[u],     Wgru[(size_t)u * G3 + j],       a0);
        a1 = fmaf(v[u + 1], Wgru[(size_t)(u + 1) * G3 + j], a1);
        a2 = fmaf(v[u + 2], Wgru[(size_t)(u + 2) * G3 + j], a2);
        a3 = fmaf(v[u + 3], Wgru[(size_t)(u + 3) * G3 + j], a3);
    }
    float r = __fadd_rn(__fadd_rn(a0, a2), __fadd_rn(a1, a3));
    if (row < 76) g_P[(size_t)row * G3 + j] = r;
    else          g_pb[j] = r;
}

__global__ void k_prepWT(const float* __restrict__ Wang,
                         const float* __restrict__ Wrad) {
    int i = blockIdx.x * 256 + threadIdx.x;
    if (i >= 76 * NU) return;
    int c = i >> 10, k = i & (NU - 1);
    g_WT[i] = (c < CA) ? Wang[(size_t)k * CA + c]
                       : Wrad[(size_t)k * CR + (c - CA)];
}

// ---------------------------------------------------------------------------
// 3xTF32 GEMM via mma.sync: g_Gh[8192,3072] = H @ U
// CTA 128x128, 8 warps (2M x 4N), warp tile 64x32, K-stage 32, 2-stage ring.
// ---------------------------------------------------------------------------
static constexpr int SM_STRIDE = 36;                   // floats per row (pad)
static constexpr int F_AHI = 0;
static constexpr int F_ALO = 128 * SM_STRIDE;          // 4608
static constexpr int F_BHI = 2 * 128 * SM_STRIDE;      // 9216
static constexpr int F_BLO = 3 * 128 * SM_STRIDE;      // 13824
static constexpr int F_STG = 4 * 128 * SM_STRIDE;      // 18432 floats / stage
static constexpr int GEMM_SMEM = 2 * F_STG * 4;        // 147456 B

__global__ __launch_bounds__(256, 1) void k_gemm_mma() {
    extern __shared__ float sm[];

    const int tid  = threadIdx.x;
    const int warp = tid >> 5, lane = tid & 31;
    const int g = lane >> 2, t = lane & 3;
    const int warp_m = warp & 1, warp_n = warp >> 1;   // 2 x 4
    const int m0cta = blockIdx.y * 128;
    const int n0cta = blockIdx.x * 128;

    float acc[4][4][4];
#pragma unroll
    for (int i = 0; i < 4; ++i)
#pragma unroll
        for (int j = 0; j < 4; ++j)
#pragma unroll
            for (int q = 0; q < 4; ++q) acc[i][j][q] = 0.0f;

    const uint32_t smem_base = smem_u32(sm);

    auto load_stage = [&](int stage, int buf) {
        const int k0 = stage * 32;
        const uint32_t sb = smem_base + (uint32_t)(buf * F_STG) * 4u;
#pragma unroll
        for (int i = 0; i < 4; ++i) {
            int c = tid + i * 256;                 // 1024 chunks each tensor
            int r = c >> 3, cc = c & 7;            // row, 16B chunk in row
            uint32_t so = (uint32_t)(r * SM_STRIDE + cc * 4) * 4u;
            size_t goA = (size_t)(m0cta + r) * NU + k0 + cc * 4;
            size_t goB = (size_t)(n0cta + r) * NU + k0 + cc * 4;
            cp16(sb + F_AHI * 4u + so, g_Hhi  + goA);
            cp16(sb + F_ALO * 4u + so, g_Hlo  + goA);
            cp16(sb + F_BHI * 4u + so, g_UhiT + goB);
            cp16(sb + F_BLO * 4u + so, g_UloT + goB);
        }
        cp_commit();
    };

    load_stage(0, 0);
    load_stage(1, 1);

    const int NSTAGE = NU / 32;   // 32
    for (int s = 0; s < NSTAGE; ++s) {
        const int buf = s & 1;
        if (s < NSTAGE - 1) cp_wait<1>(); else cp_wait<0>();
        __syncthreads();

        const float* sAh = sm + buf * F_STG + F_AHI;
        const float* sAl = sm + buf * F_STG + F_ALO;
        const float* sBh = sm + buf * F_STG + F_BHI;
        const float* sBl = sm + buf * F_STG + F_BLO;

#pragma unroll
        for (int k8 = 0; k8 < 4; ++k8) {
            const int kc = k8 * 8;
            uint32_t ahi[4][4], alo[4][4], bhi[4][2], blo[4][2];
#pragma unroll
            for (int mt = 0; mt < 4; ++mt) {
                const int r = warp_m * 64 + mt * 16 + g;
                const float* ph = sAh + r * SM_STRIDE + kc;
                const float* pl = sAl + r * SM_STRIDE + kc;
                ahi[mt][0] = __float_as_uint(ph[t]);
                ahi[mt][1] = __float_as_uint(ph[8 * SM_STRIDE + t]);
                ahi[mt][2] = __float_as_uint(ph[t + 4]);
                ahi[mt][3] = __float_as_uint(ph[8 * SM_STRIDE + t + 4]);
                alo[mt][0] = __float_as_uint(pl[t]);
                alo[mt][1] = __float_as_uint(pl[8 * SM_STRIDE + t]);
                alo[mt][2] = __float_as_uint(pl[t + 4]);
                alo[mt][3] = __float_as_uint(pl[8 * SM_STRIDE + t + 4]);
            }
#pragma unroll
            for (int nt = 0; nt < 4; ++nt) {
                const int r = warp_n * 32 + nt * 8 + g;
                const float* ph = sBh + r * SM_STRIDE + kc;
                const float* pl = sBl + r * SM_STRIDE + kc;
                bhi[nt][0] = __float_as_uint(ph[t]);
                bhi[nt][1] = __float_as_uint(ph[t + 4]);
                blo[nt][0] = __float_as_uint(pl[t]);
                blo[nt][1] = __float_as_uint(pl[t + 4]);
            }
#pragma unroll
            for (int mt = 0; mt < 4; ++mt)
#pragma unroll
                for (int nt = 0; nt < 4; ++nt) {
                    mma_tf32(acc[mt][nt], ahi[mt], bhi[nt]);
                    mma_tf32(acc[mt][nt], ahi[mt], blo[nt]);
                    mma_tf32(acc[mt][nt], alo[mt], bhi[nt]);
                }
        }
        __syncthreads();
        if (s + 2 < NSTAGE) load_stage(s + 2, buf);
    }

    // epilogue
#pragma unroll
    for (int mt = 0; mt < 4; ++mt) {
        const int row = m0cta + warp_m * 64 + mt * 16 + g;
#pragma unroll
        for (int nt = 0; nt < 4; ++nt) {
            const int col = n0cta + warp_n * 32 + nt * 8 + 2 * t;
            *(float2*)&g_Gh[(size_t)row * G3 + col] =
                make_float2(acc[mt][nt][0], acc[mt][nt][1]);
            *(float2*)&g_Gh[(size_t)(row + 8) * G3 + col] =
                make_float2(acc[mt][nt][2], acc[mt][nt][3]);
        }
    }
}

// ---------------------------------------------------------------------------
// GRU gate combine + 2-hot Gx gather + tf32 split of new h
// ---------------------------------------------------------------------------
__global__ __launch_bounds__(256) void k_combine(const float* __restrict__ bgru,
                                                 int t) {
    int i = blockIdx.x * 256 + threadIdx.x;
    int u = i & (NU - 1);
    int b = i >> 10;

    float gx0, gx1, gx2;
    if (t == 0) {
        gx0 = gx1 = gx2 = 0.0f;
    } else {
        int a  = g_Aidx[b];
        int rr = g_Ridx[b];
        const float* Pa = g_P + (size_t)a * G3;
        const float* Pr = g_P + (size_t)(CA + rr) * G3;
        gx0 = __fadd_rn(__fadd_rn(Pa[u],          Pr[u]),          g_pb[u]);
        gx1 = __fadd_rn(__fadd_rn(Pa[u + NU],     Pr[u + NU]),     g_pb[u + NU]);
        gx2 = __fadd_rn(__fadd_rn(Pa[u + 2 * NU], Pr[u + 2 * NU]), g_pb[u + 2 * NU]);
    }

    const float* gh = g_Gh + (size_t)b * G3;
    float xz = __fadd_rn(gx0, bgru[u]);
    float xr = __fadd_rn(gx1, bgru[u + NU]);
    float xn = __fadd_rn(gx2, bgru[u + 2 * NU]);
    float hz = gh[u], hr = gh[u + NU], hn = gh[u + 2 * NU];

    float z = ref_sigmoid(__fadd_rn(xz, hz));
    float r = ref_sigmoid(__fadd_rn(xr, hr));
    float n = tanhf(__fadd_rn(xn, __fmul_rn(r, hn)));
    float h = g_H[i];
    float hnew = __fadd_rn(__fmul_rn(z, h), __fmul_rn(__fsub_rn(1.0f, z), n));
    g_H[i] = hnew;
    float hi, lo;
    tf32_split(hnew, hi, lo);
    g_Hhi[i] = hi; g_Hlo[i] = lo;
}

// ---------------------------------------------------------------------------
// Logits + softmax + gumbel-argmax + outputs + indices
// ---------------------------------------------------------------------------
static constexpr int SROW = 1028;
static constexpr int SMEM_SAMPLE = (16 * SROW + 16 * 80) * 4;

__global__ __launch_bounds__(256) void k_sample(
    int t,
    const float* __restrict__ bang, const float* __restrict__ brad,
    float* __restrict__ out) {

    extern __shared__ float smf[];
    float* sh = smf;
    float* sl = smf + 16 * SROW;
    __shared__ int s_aidx[16];
    __shared__ int s_ridx[16];

    const int tid = threadIdx.x;
    const int b0 = blockIdx.x * 16;

    const float4* src = (const float4*)(g_H + (size_t)b0 * NU);
    float4* sh4 = (float4*)sh;
    for (int v = tid; v < 16 * 256; v += 256) {
        int row = v >> 8, c4 = v & 255;
        sh4[row * (SROW / 4) + c4] = src[row * 256 + c4];
    }
    __syncthreads();

    for (int l = tid; l < 16 * 76; l += 256) {
        int c = l >> 4, row = l & 15;
        const float4* w4 = (const float4*)(g_WT + (size_t)c * NU);
        const float4* h4 = sh4 + row * (SROW / 4);
        float a0 = 0.f, a1 = 0.f, a2 = 0.f, a3 = 0.f;
#pragma unroll 4
        for (int k = 0; k < 256; ++k) {
            float4 w = w4[k];
            float4 hv = h4[k];
            a0 = fmaf(hv.x, w.x, a0);
            a1 = fmaf(hv.y, w.y, a1);
            a2 = fmaf(hv.z, w.z, a2);
            a3 = fmaf(hv.w, w.w, a3);
        }
        float bias = (c < CA) ? bang[c] : brad[c - CA];
        sl[row * 80 + c] =
            __fadd_rn(__fadd_rn(__fadd_rn(a0, a2), __fadd_rn(a1, a3)), bias);
    }
    __syncthreads();

    uint32_t ka0, ka1, kr0, kr1;
    step_keys(t, ka0, ka1, kr0, kr1);

    const int wid = tid >> 5, lane = tid & 31;
    const float NEG_INF = __int_as_float(0xff800000);

    for (int rr = wid; rr < 16; rr += 8) {
        int b = b0 + rr;

        float lg = (lane < CA) ? sl[rr * 80 + lane] : NEG_INF;
        float m = lg;
#pragma unroll
        for (int off = 16; off; off >>= 1)
            m = fmaxf(m, __shfl_xor_sync(0xffffffffu, m, off));
        float e = (lane < CA) ? expf(__fsub_rn(lg, m)) : 0.0f;
        float ssum = e;
#pragma unroll
        for (int off = 16; off; off >>= 1)
            ssum += __shfl_xor_sync(0xffffffffu, ssum, off);

        float y = NEG_INF;
        if (lane < CA) {
            uint32_t j = (uint32_t)b * CA + lane;
            y = __fadd_rn(gumbel_at(ka0, ka1, j), lg);
        }
        int aidx = warp_argmax_i(y, lane);
        if (lane < CA) {
            size_t base = ((size_t)b * NT + t) * CA;
            out[OFF_AOH + base + lane] = (lane == aidx) ? 1.0f : 0.0f;
            out[OFF_APR + base + lane] = __fdiv_rn(e, ssum);
        }

        float l0v = sl[rr * 80 + CA + lane];
        float l1v = sl[rr * 80 + CA + lane + 32];
        float m2 = fmaxf(l0v, l1v);
#pragma unroll
        for (int off = 16; off; off >>= 1)
            m2 = fmaxf(m2, __shfl_xor_sync(0xffffffffu, m2, off));
        float e0 = expf(__fsub_rn(l0v, m2));
        float e1 = expf(__fsub_rn(l1v, m2));
        float s2 = e0 + e1;
#pragma unroll
        for (int off = 16; off; off >>= 1)
            s2 += __shfl_xor_sync(0xffffffffu, s2, off);

        uint32_t j0 = (uint32_t)b * CR + lane;
        float y0 = __fadd_rn(gumbel_at(kr0, kr1, j0),      l0v);
        float y1 = __fadd_rn(gumbel_at(kr0, kr1, j0 + 32), l1v);
        float yb; int ib;
        if (y1 > y0) { yb = y1; ib = lane + 32; } else { yb = y0; ib = lane; }
        int ridx = warp_argmax_i(yb, ib);

        size_t baser = ((size_t)b * NT + t) * CR;
        out[OFF_ROH + baser + lane]      = (ridx == lane)      ? 1.0f : 0.0f;
        out[OFF_ROH + baser + lane + 32] = (ridx == lane + 32) ? 1.0f : 0.0f;
        out[OFF_RPR + baser + lane]      = __fdiv_rn(e0, s2);
        out[OFF_RPR + baser + lane + 32] = __fdiv_rn(e1, s2);

        if (lane == 0) { s_aidx[rr] = aidx; s_ridx[rr] = ridx; }
    }
    __syncthreads();

    if (tid < 16) {
        g_Aidx[b0 + tid] = s_aidx[tid];
        g_Ridx[b0 + tid] = s_ridx[tid];
    }
}

// ---------------------------------------------------------------------------
// Launch
// ---------------------------------------------------------------------------
extern "C" void kernel_launch(void* const* d_in, const int* in_sizes, int n_in,
                              void* d_out, int out_size) {
    const float* s    = (const float*)d_in[0];
    const float* Wenc = (const float*)d_in[1];
    const float* benc = (const float*)d_in[2];
    const float* Wgru = (const float*)d_in[3];
    const float* Ugru = (const float*)d_in[4];
    const float* bgru = (const float*)d_in[5];
    const float* Wang = (const float*)d_in[6];
    const float* bang = (const float*)d_in[7];
    const float* Wrad = (const float*)d_in[8];
    const float* brad = (const float*)d_in[9];
    float* out = (float*)d_out;

    cudaFuncSetAttribute(k_sample, cudaFuncAttributeMaxDynamicSharedMemorySize,
                         SMEM_SAMPLE);
    cudaFuncSetAttribute(k_gemm_mma, cudaFuncAttributeMaxDynamicSharedMemorySize,
                         GEMM_SMEM);

    k_init<<<(B_SZ * NU + 255) / 256, 256>>>(s);
    k_prepU<<<((size_t)G3 * NU + 255) / 256, 256>>>(Ugru);
    k_prepP<<<dim3(G3 / 256, 77), 256>>>(Wenc, benc, Wgru);
    k_prepWT<<<(76 * NU + 255) / 256, 256>>>(Wang, Wrad);

    for (int t = 0; t < NT; ++t) {
        k_gemm_mma<<<dim3(G3 / 128, B_SZ / 128), 256, GEMM_SMEM>>>();
        k_combine<<<(B_SZ * NU) / 256, 256>>>(bgru, t);
        k_sample<<<B_SZ / 16, 256, SMEM_SAMPLE>>>(t, bang, brad, out);
    }
}